// round 5
// baseline (speedup 1.0000x reference)
#include <cuda_runtime.h>
#include <math.h>

#define BMAX 8192
#define NJC 16
#define IT 128

// ---------------- scratch (device globals: no allocation allowed) ----------------
__device__ float  g_feat[BMAX * 784];
__device__ __align__(16) float g_proj_raw[BMAX * 4];
__device__ __align__(16) float g_proj[BMAX * 4];
__device__ __align__(16) float g_pn[BMAX * 4];
__device__ float  g_stats[8];
__device__ __align__(16) float g_wp[NJC * BMAX * 4];
__device__ float  g_srow[BMAX];
__device__ float  g_S;

// Accumulate one input row into 7 pooled-column conv accumulators.
// CRITICAL: sequential fmaf in FORWARD tap order (w0,w1,w2); rows ascending,
// channels ascending at call sites -> bit-exact with the round-1 proj chain.
template<int O>
__device__ __forceinline__ void rowacc(const float* __restrict__ f,
                                       const float* __restrict__ w,
                                       float* __restrict__ sa, float* __restrict__ sb)
{
    #pragma unroll
    for (int p = 0; p < 7; p++) {
        sa[p] = fmaf(w[0], f[O + 2 * p],     sa[p]);
        sa[p] = fmaf(w[1], f[O + 2 * p + 1], sa[p]);
        sa[p] = fmaf(w[2], f[O + 2 * p + 2], sa[p]);
        sb[p] = fmaf(w[0], f[O + 2 * p + 1], sb[p]);
        sb[p] = fmaf(w[1], f[O + 2 * p + 2], sb[p]);
        sb[p] = fmaf(w[2], f[O + 2 * p + 3], sb[p]);
    }
}

// ================= K1: conv1+relu+pool + conv2+relu+pool (one image / block) ==========
__global__ __launch_bounds__(128) void k_conv(
    const float* __restrict__ x, const float* __restrict__ w1, const float* __restrict__ b1,
    const float* __restrict__ w2, const float* __restrict__ b2)
{
    __shared__ float xp[30 * 32];        // padded input 30 rows x 32-stride (28x28 at +1,+1)
    __shared__ float h1[8 * 16 * 16];    // conv1 pooled output, per channel 16x16 padded
    __shared__ float sw1[72], sb1[8], sw2[1152], sb2[16];

    const int img = blockIdx.x;
    const int tid = threadIdx.x;

    for (int i = tid; i < 960; i += 128) xp[i] = 0.f;
    for (int i = tid; i < 2048; i += 128) h1[i] = 0.f;
    if (tid < 72) sw1[tid] = w1[tid];
    if (tid < 8)  sb1[tid] = b1[tid];
    for (int i = tid; i < 1152; i += 128) sw2[i] = w2[i];
    if (tid < 16) sb2[tid] = b2[tid];
    __syncthreads();

    const float* xi = x + (size_t)img * 784;
    for (int i = tid; i < 784; i += 128) {
        int y = i / 28, xx = i - y * 28;
        xp[(y + 1) * 32 + (xx + 1)] = xi[i];
    }
    __syncthreads();

    // ---- conv1 (1->8) + relu + pool. thread = (c, py): 14 pooled cols in 2 groups of 7.
    if (tid < 112) {
        const int c = tid / 14, py = tid - (tid / 14) * 14;
        float w[9];
        #pragma unroll
        for (int k = 0; k < 9; k++) w[k] = sw1[c * 9 + k];
        const float bias = sb1[c];

        #pragma unroll
        for (int g = 0; g < 2; g++) {
            const int cb = g ? 12 : 0;            // float4-aligned base col
            float s0[7] = {}, s1[7] = {}, s2[7] = {}, s3[7] = {};
            #pragma unroll
            for (int r = 0; r < 4; r++) {
                const float4* rp = (const float4*)(xp + (2 * py + r) * 32 + cb);
                float f[20];
                #pragma unroll
                for (int k = 0; k < 5; k++) {
                    float4 q = rp[k];
                    f[4 * k] = q.x; f[4 * k + 1] = q.y; f[4 * k + 2] = q.z; f[4 * k + 3] = q.w;
                }
                if (g == 0) {
                    if (r == 0)  rowacc<0>(f, w + 0, s0, s1);
                    if (r == 1) { rowacc<0>(f, w + 3, s0, s1); rowacc<0>(f, w + 0, s2, s3); }
                    if (r == 2) { rowacc<0>(f, w + 6, s0, s1); rowacc<0>(f, w + 3, s2, s3); }
                    if (r == 3)  rowacc<0>(f, w + 6, s2, s3);
                } else {
                    if (r == 0)  rowacc<2>(f, w + 0, s0, s1);
                    if (r == 1) { rowacc<2>(f, w + 3, s0, s1); rowacc<2>(f, w + 0, s2, s3); }
                    if (r == 2) { rowacc<2>(f, w + 6, s0, s1); rowacc<2>(f, w + 3, s2, s3); }
                    if (r == 3)  rowacc<2>(f, w + 6, s2, s3);
                }
            }
            #pragma unroll
            for (int p = 0; p < 7; p++) {
                float m = fmaxf(fmaxf(s0[p], s1[p]), fmaxf(s2[p], s3[p])) + bias;
                int px = g * 7 + p;
                h1[c * 256 + (py + 1) * 16 + (px + 1)] = fmaxf(m, 0.f);
            }
        }
    }
    __syncthreads();

    // ---- conv2 (8->16) + relu + pool. thread = (co, py): 7 pooled cols.
    // ci loop NOT unrolled: keeps the hot body ~4.5KB so it fits the 6KB L0 I$.
    // (Full unroll = ~32KB straight-line body -> I-cache-fetch bound; R2/R4 regression.)
    if (tid < 112) {
        const int co = tid / 7, py = tid - (tid / 7) * 7;
        float s0[7] = {}, s1[7] = {}, s2[7] = {}, s3[7] = {};

        #pragma unroll 1
        for (int ci = 0; ci < 8; ci++) {
            float w[9];
            #pragma unroll
            for (int k = 0; k < 9; k++) w[k] = sw2[(co * 8 + ci) * 9 + k];
            const float* hb = h1 + ci * 256;
            #pragma unroll
            for (int r = 0; r < 4; r++) {
                const float4* rp = (const float4*)(hb + (2 * py + r) * 16);
                float f[16];
                #pragma unroll
                for (int k = 0; k < 4; k++) {
                    float4 q = rp[k];
                    f[4 * k] = q.x; f[4 * k + 1] = q.y; f[4 * k + 2] = q.z; f[4 * k + 3] = q.w;
                }
                if (r == 0)  rowacc<0>(f, w + 0, s0, s1);
                if (r == 1) { rowacc<0>(f, w + 3, s0, s1); rowacc<0>(f, w + 0, s2, s3); }
                if (r == 2) { rowacc<0>(f, w + 6, s0, s1); rowacc<0>(f, w + 3, s2, s3); }
                if (r == 3)  rowacc<0>(f, w + 6, s2, s3);
            }
        }
        const float bias = sb2[co];
        float* fo = g_feat + (size_t)img * 784;
        #pragma unroll
        for (int p = 0; p < 7; p++) {
            float m = fmaxf(fmaxf(s0[p], s1[p]), fmaxf(s2[p], s3[p])) + bias;
            fo[co * 49 + py * 7 + p] = fmaxf(m, 0.f);
        }
    }
}

// ================= K2: fc1 (784->64, relu) + fc2 (64->4), 64 images / block ==========
#define KT 56
__global__ __launch_bounds__(256) void k_fc(
    const float* __restrict__ w1, const float* __restrict__ b1,
    const float* __restrict__ w2, const float* __restrict__ b2, int B)
{
    __shared__ float As[64][KT + 1];
    __shared__ float Ws[64][KT + 1];
    __shared__ float Hs[64][65];

    const int i0 = blockIdx.x * 64;
    const int tid = threadIdx.x;
    const int tx = tid & 15, ty = tid >> 4;

    float acc[4][4] = {};

    for (int k0 = 0; k0 < 784; k0 += KT) {
        for (int e = tid; e < 64 * KT; e += 256) {
            int r = e / KT, kk = e - r * KT;
            int row = i0 + r;
            As[r][kk] = (row < B) ? g_feat[(size_t)row * 784 + k0 + kk] : 0.f;
            Ws[r][kk] = w1[r * 784 + k0 + kk];
        }
        __syncthreads();
        #pragma unroll 4
        for (int kk = 0; kk < KT; kk++) {
            float a[4], b[4];
            #pragma unroll
            for (int r = 0; r < 4; r++) a[r] = As[ty * 4 + r][kk];
            #pragma unroll
            for (int c = 0; c < 4; c++) b[c] = Ws[tx * 4 + c][kk];
            #pragma unroll
            for (int r = 0; r < 4; r++)
                #pragma unroll
                for (int c = 0; c < 4; c++)
                    acc[r][c] += a[r] * b[c];
        }
        __syncthreads();
    }

    #pragma unroll
    for (int r = 0; r < 4; r++)
        #pragma unroll
        for (int c = 0; c < 4; c++) {
            int o = tx * 4 + c;
            Hs[ty * 4 + r][o] = fmaxf(acc[r][c] + b1[o], 0.f);
        }
    __syncthreads();

    int m = tid >> 2, c4 = tid & 3;
    if (i0 + m < B) {
        float s = b2[c4];
        #pragma unroll
        for (int o = 0; o < 64; o++) s += w2[c4 * 64 + o] * Hs[m][o];
        g_proj_raw[(size_t)(i0 + m) * 4 + c4] = s;
    }
}

// ================= K3: batchnorm stats (single block) =================
__global__ __launch_bounds__(1024) void k_bnstats(int B)
{
    __shared__ float red[32][8];
    const int tid = threadIdx.x;
    float s0 = 0, s1 = 0, s2 = 0, s3 = 0, q0 = 0, q1 = 0, q2 = 0, q3 = 0;
    const float4* pr = (const float4*)g_proj_raw;
    for (int i = tid; i < B; i += 1024) {
        float4 v = pr[i];
        s0 += v.x; s1 += v.y; s2 += v.z; s3 += v.w;
        q0 += v.x * v.x; q1 += v.y * v.y; q2 += v.z * v.z; q3 += v.w * v.w;
    }
    #pragma unroll
    for (int o = 16; o > 0; o >>= 1) {
        s0 += __shfl_down_sync(0xffffffffu, s0, o);
        s1 += __shfl_down_sync(0xffffffffu, s1, o);
        s2 += __shfl_down_sync(0xffffffffu, s2, o);
        s3 += __shfl_down_sync(0xffffffffu, s3, o);
        q0 += __shfl_down_sync(0xffffffffu, q0, o);
        q1 += __shfl_down_sync(0xffffffffu, q1, o);
        q2 += __shfl_down_sync(0xffffffffu, q2, o);
        q3 += __shfl_down_sync(0xffffffffu, q3, o);
    }
    int warp = tid >> 5, lane = tid & 31;
    if (lane == 0) {
        red[warp][0] = s0; red[warp][1] = s1; red[warp][2] = s2; red[warp][3] = s3;
        red[warp][4] = q0; red[warp][5] = q1; red[warp][6] = q2; red[warp][7] = q3;
    }
    __syncthreads();
    if (tid < 8) {
        float a = 0.f;
        for (int w = 0; w < 32; w++) a += red[w][tid];
        red[0][tid] = a;
    }
    __syncthreads();
    if (tid < 4) {
        float invB = 1.f / (float)B;
        float mean = red[0][tid] * invB;
        float var  = red[0][4 + tid] * invB - mean * mean;
        g_stats[tid] = mean;
        g_stats[4 + tid] = rsqrtf(var + 1e-5f);
    }
    if (tid == 0) g_S = 0.f;
}

// ================= K4: apply BN + row-normalize =================
__global__ __launch_bounds__(256) void k_bnapply(
    const float* __restrict__ gamma, const float* __restrict__ beta, int B)
{
    int i = blockIdx.x * 256 + threadIdx.x;
    if (i >= B) return;
    float4 v = ((const float4*)g_proj_raw)[i];
    float p0 = (v.x - g_stats[0]) * g_stats[4] * gamma[0] + beta[0];
    float p1 = (v.y - g_stats[1]) * g_stats[5] * gamma[1] + beta[1];
    float p2 = (v.z - g_stats[2]) * g_stats[6] * gamma[2] + beta[2];
    float p3 = (v.w - g_stats[3]) * g_stats[7] * gamma[3] + beta[3];
    float inv = 1.f / (sqrtf(p0 * p0 + p1 * p1 + p2 * p2 + p3 * p3) + 1e-12f);
    ((float4*)g_proj)[i] = make_float4(p0, p1, p2, p3);
    ((float4*)g_pn)[i]   = make_float4(p0 * inv, p1 * inv, p2 * inv, p3 * inv);
}

// ================= K5: pairwise adjacency-weighted sum =================
// 2 i-rows / thread (scalar), self-pair included (subtracted exactly in k_combine).
#define TJ 256
__global__ __launch_bounds__(IT) void k_pair(int B)
{
    __shared__ float4 pns[TJ];
    __shared__ float4 prs[TJ];
    const int tid = threadIdx.x;
    const int ib  = blockIdx.x * (2 * IT);
    const int i1  = ib + tid;
    const int i2  = ib + IT + tid;
    const int jc  = blockIdx.y;
    const int chunk = (B + NJC - 1) / NJC;
    const int jbeg = jc * chunk;
    const int jend = min(jbeg + chunk, B);

    const float4* pn   = (const float4*)g_pn;
    const float4* proj = (const float4*)g_proj;

    float4 v1 = (i1 < B) ? pn[i1] : make_float4(0.f, 0.f, 0.f, 0.f);
    float4 v2 = (i2 < B) ? pn[i2] : make_float4(0.f, 0.f, 0.f, 0.f);
    float w10 = 0.f, w11 = 0.f, w12 = 0.f, w13 = 0.f;
    float w20 = 0.f, w21 = 0.f, w22 = 0.f, w23 = 0.f;

    for (int jb = jbeg; jb < jend; jb += TJ) {
        int n = jend - jb;
        for (int t = tid; t < TJ; t += IT) {
            if (t < n) { pns[t] = pn[jb + t]; prs[t] = proj[jb + t]; }
            else       { pns[t] = make_float4(0.f, 0.f, 0.f, 0.f);
                         prs[t] = make_float4(0.f, 0.f, 0.f, 0.f); }
        }
        __syncthreads();
        #pragma unroll 8
        for (int jj = 0; jj < TJ; jj++) {
            float4 q  = pns[jj];
            float4 pj = prs[jj];

            float d1 = v1.x * q.x + v1.y * q.y + v1.z * q.z + v1.w * q.w;
            float s1 = (d1 * d1 >= 0.9f) ? 1.f : 0.f;
            w10 = fmaf(s1, pj.x, w10); w11 = fmaf(s1, pj.y, w11);
            w12 = fmaf(s1, pj.z, w12); w13 = fmaf(s1, pj.w, w13);

            float d2 = v2.x * q.x + v2.y * q.y + v2.z * q.z + v2.w * q.w;
            float s2 = (d2 * d2 >= 0.9f) ? 1.f : 0.f;
            w20 = fmaf(s2, pj.x, w20); w21 = fmaf(s2, pj.y, w21);
            w22 = fmaf(s2, pj.z, w22); w23 = fmaf(s2, pj.w, w23);
        }
        __syncthreads();
    }
    float4* wp = (float4*)g_wp;
    if (i1 < B) wp[(size_t)jc * B + i1] = make_float4(w10, w11, w12, w13);
    if (i2 < B) wp[(size_t)jc * B + i2] = make_float4(w20, w21, w22, w23);
}

// ================= K6: combine partials (subtract self), row sums, diff^2 ==========
__global__ __launch_bounds__(256) void k_combine(int B)
{
    int i = blockIdx.x * 256 + threadIdx.x;
    float ds = 0.f;
    if (i < B) {
        const float4* wpp = (const float4*)g_wp;
        float4 w = wpp[i];
        #pragma unroll
        for (int jc = 1; jc < NJC; jc++) {
            float4 t = wpp[(size_t)jc * B + i];
            w.x += t.x; w.y += t.y; w.z += t.z; w.w += t.w;
        }
        float4 p = ((const float4*)g_proj)[i];
        // subtract self-pair contribution (off-diagonal mask in reference)
        w.x -= p.x; w.y -= p.y; w.z -= p.z; w.w -= p.w;
        g_srow[i] = p.x + p.y + p.z + p.w + w.x + w.y + w.z + w.w;
        float d0 = p.x - w.x, d1 = p.y - w.y, d2 = p.z - w.z, d3 = p.w - w.w;
        ds = d0 * d0 + d1 * d1 + d2 * d2 + d3 * d3;
    }
    #pragma unroll
    for (int o = 16; o > 0; o >>= 1) ds += __shfl_down_sync(0xffffffffu, ds, o);
    __shared__ float red[8];
    int warp = threadIdx.x >> 5, lane = threadIdx.x & 31;
    if (lane == 0) red[warp] = ds;
    __syncthreads();
    if (threadIdx.x == 0) {
        float t = 0.f;
        #pragma unroll
        for (int w = 0; w < 8; w++) t += red[w];
        atomicAdd(&g_S, t);
    }
}

// ================= K7: kernel value + sigmoid epilogue =================
__global__ __launch_bounds__(256) void k_final(float* __restrict__ out, int B)
{
    int i = blockIdx.x * 256 + threadIdx.x;
    if (i >= B) return;
    float kv = expf(-g_S);              // GAMMA = 1
    float logit = g_srow[i] + kv;       // SHIFT = 0
    float p = 1.f / (1.f + expf(-logit));
    out[2 * i]     = p;
    out[2 * i + 1] = 1.f - p;
}

// ================= launcher =================
extern "C" void kernel_launch(void* const* d_in, const int* in_sizes, int n_in,
                              void* d_out, int out_size)
{
    const float* x   = (const float*)d_in[0];
    const float* c1w = (const float*)d_in[1];
    const float* c1b = (const float*)d_in[2];
    const float* c2w = (const float*)d_in[3];
    const float* c2b = (const float*)d_in[4];
    const float* f1w = (const float*)d_in[5];
    const float* f1b = (const float*)d_in[6];
    const float* f2w = (const float*)d_in[7];
    const float* f2b = (const float*)d_in[8];
    const float* gam = (const float*)d_in[9];
    const float* bet = (const float*)d_in[10];
    float* out = (float*)d_out;

    const int B = in_sizes[0] / 784;

    k_conv<<<B, 128>>>(x, c1w, c1b, c2w, c2b);
    k_fc<<<(B + 63) / 64, 256>>>(f1w, f1b, f2w, f2b, B);
    k_bnstats<<<1, 1024>>>(B);
    k_bnapply<<<(B + 255) / 256, 256>>>(gam, bet, B);
    dim3 gp((B + 2 * IT - 1) / (2 * IT), NJC);
    k_pair<<<gp, IT>>>(B);
    k_combine<<<(B + 255) / 256, 256>>>(B);
    k_final<<<(B + 255) / 256, 256>>>(out, B);
}

// round 6
// speedup vs baseline: 1.3632x; 1.3632x over previous
#include <cuda_runtime.h>
#include <math.h>

#define BMAX 8192
#define NJC 16
#define IT 128

// ---------------- scratch (device globals: no allocation allowed) ----------------
__device__ float  g_feat[BMAX * 784];
__device__ __align__(16) float g_proj_raw[BMAX * 4];
__device__ __align__(16) float g_proj[BMAX * 4];
__device__ __align__(16) float g_pn[BMAX * 4];
__device__ float  g_stats[8];
__device__ __align__(16) float g_wp[NJC * BMAX * 4];
__device__ float  g_srow[BMAX];
__device__ float  g_S;

// ================= K1: conv1+relu+pool + conv2+relu+pool (one image / block) =========
// EXACT round-1 version (456.7us baseline). Restructured variants all regressed.
__global__ __launch_bounds__(128) void k_conv(
    const float* __restrict__ x, const float* __restrict__ w1, const float* __restrict__ b1,
    const float* __restrict__ w2, const float* __restrict__ b2)
{
    __shared__ float xp[30 * 30];        // padded input 28x28 -> 30x30
    __shared__ float h1[8 * 16 * 16];    // padded h1 14x14 -> 16x16 per channel
    __shared__ float sw1[72], sb1[8], sw2[1152], sb2[16];

    const int img = blockIdx.x;
    const int tid = threadIdx.x;

    for (int i = tid; i < 900; i += 128) xp[i] = 0.f;
    for (int i = tid; i < 2048; i += 128) h1[i] = 0.f;
    if (tid < 72) sw1[tid] = w1[tid];
    if (tid < 8)  sb1[tid] = b1[tid];
    for (int i = tid; i < 1152; i += 128) sw2[i] = w2[i];
    if (tid < 16) sb2[tid] = b2[tid];
    __syncthreads();

    const float* xi = x + (size_t)img * 784;
    for (int i = tid; i < 784; i += 128) {
        int y = i / 28, xx = i % 28;
        xp[(y + 1) * 30 + (xx + 1)] = xi[i];
    }
    __syncthreads();

    // conv1 (SAME, 3x3) + relu + 2x2 maxpool -> h1[c][1+py][1+px]
    for (int idx = tid; idx < 8 * 196; idx += 128) {
        int c = idx / 196, p = idx % 196;
        int py = p / 14, px = p % 14;
        int y0 = 2 * py, x0 = 2 * px;
        float v[4][4];
        #pragma unroll
        for (int dy = 0; dy < 4; dy++)
            #pragma unroll
            for (int dx = 0; dx < 4; dx++)
                v[dy][dx] = xp[(y0 + dy) * 30 + x0 + dx];
        const float* w = sw1 + c * 9;
        float s00 = 0.f, s01 = 0.f, s10 = 0.f, s11 = 0.f;
        #pragma unroll
        for (int dy = 0; dy < 3; dy++)
            #pragma unroll
            for (int dx = 0; dx < 3; dx++) {
                float ww = w[dy * 3 + dx];
                s00 += ww * v[dy][dx];
                s01 += ww * v[dy][dx + 1];
                s10 += ww * v[dy + 1][dx];
                s11 += ww * v[dy + 1][dx + 1];
            }
        float m = fmaxf(fmaxf(s00, s01), fmaxf(s10, s11)) + sb1[c];
        h1[c * 256 + (py + 1) * 16 + (px + 1)] = fmaxf(m, 0.f);
    }
    __syncthreads();

    // conv2 (8->16, SAME, 3x3) + relu + 2x2 maxpool -> g_feat (flattened NCHW)
    float* fo = g_feat + (size_t)img * 784;
    for (int idx = tid; idx < 16 * 49; idx += 128) {
        int co = idx / 49, p = idx % 49;
        int py = p / 7, px = p % 7;
        int y0 = 2 * py, x0 = 2 * px;
        float s00 = 0.f, s01 = 0.f, s10 = 0.f, s11 = 0.f;
        #pragma unroll
        for (int ci = 0; ci < 8; ci++) {
            const float* w = sw2 + (co * 8 + ci) * 9;
            const float* hb = h1 + ci * 256;
            float v[4][4];
            #pragma unroll
            for (int dy = 0; dy < 4; dy++)
                #pragma unroll
                for (int dx = 0; dx < 4; dx++)
                    v[dy][dx] = hb[(y0 + dy) * 16 + x0 + dx];
            #pragma unroll
            for (int dy = 0; dy < 3; dy++)
                #pragma unroll
                for (int dx = 0; dx < 3; dx++) {
                    float ww = w[dy * 3 + dx];
                    s00 += ww * v[dy][dx];
                    s01 += ww * v[dy][dx + 1];
                    s10 += ww * v[dy + 1][dx];
                    s11 += ww * v[dy + 1][dx + 1];
                }
        }
        float m = fmaxf(fmaxf(s00, s01), fmaxf(s10, s11)) + sb2[co];
        fo[co * 49 + py * 7 + px] = fmaxf(m, 0.f);
    }
}

// ================= K2: fc1 (784->64, relu) + fc2 (64->4), 64 images / block ==========
#define KT 56
__global__ __launch_bounds__(256) void k_fc(
    const float* __restrict__ w1, const float* __restrict__ b1,
    const float* __restrict__ w2, const float* __restrict__ b2, int B)
{
    __shared__ float As[64][KT + 1];
    __shared__ float Ws[64][KT + 1];
    __shared__ float Hs[64][65];

    const int i0 = blockIdx.x * 64;
    const int tid = threadIdx.x;
    const int tx = tid & 15, ty = tid >> 4;

    float acc[4][4] = {};

    for (int k0 = 0; k0 < 784; k0 += KT) {
        for (int e = tid; e < 64 * KT; e += 256) {
            int r = e / KT, kk = e - r * KT;
            int row = i0 + r;
            As[r][kk] = (row < B) ? g_feat[(size_t)row * 784 + k0 + kk] : 0.f;
            Ws[r][kk] = w1[r * 784 + k0 + kk];
        }
        __syncthreads();
        #pragma unroll 4
        for (int kk = 0; kk < KT; kk++) {
            float a[4], b[4];
            #pragma unroll
            for (int r = 0; r < 4; r++) a[r] = As[ty * 4 + r][kk];
            #pragma unroll
            for (int c = 0; c < 4; c++) b[c] = Ws[tx * 4 + c][kk];
            #pragma unroll
            for (int r = 0; r < 4; r++)
                #pragma unroll
                for (int c = 0; c < 4; c++)
                    acc[r][c] += a[r] * b[c];
        }
        __syncthreads();
    }

    #pragma unroll
    for (int r = 0; r < 4; r++)
        #pragma unroll
        for (int c = 0; c < 4; c++) {
            int o = tx * 4 + c;
            Hs[ty * 4 + r][o] = fmaxf(acc[r][c] + b1[o], 0.f);
        }
    __syncthreads();

    int m = tid >> 2, c4 = tid & 3;
    if (i0 + m < B) {
        float s = b2[c4];
        #pragma unroll
        for (int o = 0; o < 64; o++) s += w2[c4 * 64 + o] * Hs[m][o];
        g_proj_raw[(size_t)(i0 + m) * 4 + c4] = s;
    }
}

// ================= K3: batchnorm stats (single block) =================
__global__ __launch_bounds__(1024) void k_bnstats(int B)
{
    __shared__ float red[32][8];
    const int tid = threadIdx.x;
    float s0 = 0, s1 = 0, s2 = 0, s3 = 0, q0 = 0, q1 = 0, q2 = 0, q3 = 0;
    const float4* pr = (const float4*)g_proj_raw;
    for (int i = tid; i < B; i += 1024) {
        float4 v = pr[i];
        s0 += v.x; s1 += v.y; s2 += v.z; s3 += v.w;
        q0 += v.x * v.x; q1 += v.y * v.y; q2 += v.z * v.z; q3 += v.w * v.w;
    }
    #pragma unroll
    for (int o = 16; o > 0; o >>= 1) {
        s0 += __shfl_down_sync(0xffffffffu, s0, o);
        s1 += __shfl_down_sync(0xffffffffu, s1, o);
        s2 += __shfl_down_sync(0xffffffffu, s2, o);
        s3 += __shfl_down_sync(0xffffffffu, s3, o);
        q0 += __shfl_down_sync(0xffffffffu, q0, o);
        q1 += __shfl_down_sync(0xffffffffu, q1, o);
        q2 += __shfl_down_sync(0xffffffffu, q2, o);
        q3 += __shfl_down_sync(0xffffffffu, q3, o);
    }
    int warp = tid >> 5, lane = tid & 31;
    if (lane == 0) {
        red[warp][0] = s0; red[warp][1] = s1; red[warp][2] = s2; red[warp][3] = s3;
        red[warp][4] = q0; red[warp][5] = q1; red[warp][6] = q2; red[warp][7] = q3;
    }
    __syncthreads();
    if (tid < 8) {
        float a = 0.f;
        for (int w = 0; w < 32; w++) a += red[w][tid];
        red[0][tid] = a;
    }
    __syncthreads();
    if (tid < 4) {
        float invB = 1.f / (float)B;
        float mean = red[0][tid] * invB;
        float var  = red[0][4 + tid] * invB - mean * mean;
        g_stats[tid] = mean;
        g_stats[4 + tid] = rsqrtf(var + 1e-5f);
    }
    if (tid == 0) g_S = 0.f;
}

// ================= K4: apply BN + row-normalize =================
__global__ __launch_bounds__(256) void k_bnapply(
    const float* __restrict__ gamma, const float* __restrict__ beta, int B)
{
    int i = blockIdx.x * 256 + threadIdx.x;
    if (i >= B) return;
    float4 v = ((const float4*)g_proj_raw)[i];
    float p0 = (v.x - g_stats[0]) * g_stats[4] * gamma[0] + beta[0];
    float p1 = (v.y - g_stats[1]) * g_stats[5] * gamma[1] + beta[1];
    float p2 = (v.z - g_stats[2]) * g_stats[6] * gamma[2] + beta[2];
    float p3 = (v.w - g_stats[3]) * g_stats[7] * gamma[3] + beta[3];
    float inv = 1.f / (sqrtf(p0 * p0 + p1 * p1 + p2 * p2 + p3 * p3) + 1e-12f);
    ((float4*)g_proj)[i] = make_float4(p0, p1, p2, p3);
    ((float4*)g_pn)[i]   = make_float4(p0 * inv, p1 * inv, p2 * inv, p3 * inv);
}

// ================= K5: pairwise adjacency-weighted sum =================
// 2 i-rows / thread, self-pair included (subtracted exactly in k_combine).
// Validated bit-exact in R4/R5 (rel_err 5.845535e-4).
#define TJ 256
__global__ __launch_bounds__(IT) void k_pair(int B)
{
    __shared__ float4 pns[TJ];
    __shared__ float4 prs[TJ];
    const int tid = threadIdx.x;
    const int ib  = blockIdx.x * (2 * IT);
    const int i1  = ib + tid;
    const int i2  = ib + IT + tid;
    const int jc  = blockIdx.y;
    const int chunk = (B + NJC - 1) / NJC;
    const int jbeg = jc * chunk;
    const int jend = min(jbeg + chunk, B);

    const float4* pn   = (const float4*)g_pn;
    const float4* proj = (const float4*)g_proj;

    float4 v1 = (i1 < B) ? pn[i1] : make_float4(0.f, 0.f, 0.f, 0.f);
    float4 v2 = (i2 < B) ? pn[i2] : make_float4(0.f, 0.f, 0.f, 0.f);
    float w10 = 0.f, w11 = 0.f, w12 = 0.f, w13 = 0.f;
    float w20 = 0.f, w21 = 0.f, w22 = 0.f, w23 = 0.f;

    for (int jb = jbeg; jb < jend; jb += TJ) {
        int n = jend - jb;
        for (int t = tid; t < TJ; t += IT) {
            if (t < n) { pns[t] = pn[jb + t]; prs[t] = proj[jb + t]; }
            else       { pns[t] = make_float4(0.f, 0.f, 0.f, 0.f);
                         prs[t] = make_float4(0.f, 0.f, 0.f, 0.f); }
        }
        __syncthreads();
        #pragma unroll 8
        for (int jj = 0; jj < TJ; jj++) {
            float4 q  = pns[jj];
            float4 pj = prs[jj];

            float d1 = v1.x * q.x + v1.y * q.y + v1.z * q.z + v1.w * q.w;
            float s1 = (d1 * d1 >= 0.9f) ? 1.f : 0.f;
            w10 = fmaf(s1, pj.x, w10); w11 = fmaf(s1, pj.y, w11);
            w12 = fmaf(s1, pj.z, w12); w13 = fmaf(s1, pj.w, w13);

            float d2 = v2.x * q.x + v2.y * q.y + v2.z * q.z + v2.w * q.w;
            float s2 = (d2 * d2 >= 0.9f) ? 1.f : 0.f;
            w20 = fmaf(s2, pj.x, w20); w21 = fmaf(s2, pj.y, w21);
            w22 = fmaf(s2, pj.z, w22); w23 = fmaf(s2, pj.w, w23);
        }
        __syncthreads();
    }
    float4* wp = (float4*)g_wp;
    if (i1 < B) wp[(size_t)jc * B + i1] = make_float4(w10, w11, w12, w13);
    if (i2 < B) wp[(size_t)jc * B + i2] = make_float4(w20, w21, w22, w23);
}

// ================= K6: combine partials (subtract self), row sums, diff^2 ==========
__global__ __launch_bounds__(256) void k_combine(int B)
{
    int i = blockIdx.x * 256 + threadIdx.x;
    float ds = 0.f;
    if (i < B) {
        const float4* wpp = (const float4*)g_wp;
        float4 w = wpp[i];
        #pragma unroll
        for (int jc = 1; jc < NJC; jc++) {
            float4 t = wpp[(size_t)jc * B + i];
            w.x += t.x; w.y += t.y; w.z += t.z; w.w += t.w;
        }
        float4 p = ((const float4*)g_proj)[i];
        // subtract self-pair contribution (off-diagonal mask in reference)
        w.x -= p.x; w.y -= p.y; w.z -= p.z; w.w -= p.w;
        g_srow[i] = p.x + p.y + p.z + p.w + w.x + w.y + w.z + w.w;
        float d0 = p.x - w.x, d1 = p.y - w.y, d2 = p.z - w.z, d3 = p.w - w.w;
        ds = d0 * d0 + d1 * d1 + d2 * d2 + d3 * d3;
    }
    #pragma unroll
    for (int o = 16; o > 0; o >>= 1) ds += __shfl_down_sync(0xffffffffu, ds, o);
    __shared__ float red[8];
    int warp = threadIdx.x >> 5, lane = threadIdx.x & 31;
    if (lane == 0) red[warp] = ds;
    __syncthreads();
    if (threadIdx.x == 0) {
        float t = 0.f;
        #pragma unroll
        for (int w = 0; w < 8; w++) t += red[w];
        atomicAdd(&g_S, t);
    }
}

// ================= K7: kernel value + sigmoid epilogue =================
__global__ __launch_bounds__(256) void k_final(float* __restrict__ out, int B)
{
    int i = blockIdx.x * 256 + threadIdx.x;
    if (i >= B) return;
    float kv = expf(-g_S);              // GAMMA = 1
    float logit = g_srow[i] + kv;       // SHIFT = 0
    float p = 1.f / (1.f + expf(-logit));
    out[2 * i]     = p;
    out[2 * i + 1] = 1.f - p;
}

// ================= launcher =================
extern "C" void kernel_launch(void* const* d_in, const int* in_sizes, int n_in,
                              void* d_out, int out_size)
{
    const float* x   = (const float*)d_in[0];
    const float* c1w = (const float*)d_in[1];
    const float* c1b = (const float*)d_in[2];
    const float* c2w = (const float*)d_in[3];
    const float* c2b = (const float*)d_in[4];
    const float* f1w = (const float*)d_in[5];
    const float* f1b = (const float*)d_in[6];
    const float* f2w = (const float*)d_in[7];
    const float* f2b = (const float*)d_in[8];
    const float* gam = (const float*)d_in[9];
    const float* bet = (const float*)d_in[10];
    float* out = (float*)d_out;

    const int B = in_sizes[0] / 784;

    k_conv<<<B, 128>>>(x, c1w, c1b, c2w, c2b);
    k_fc<<<(B + 63) / 64, 256>>>(f1w, f1b, f2w, f2b, B);
    k_bnstats<<<1, 1024>>>(B);
    k_bnapply<<<(B + 255) / 256, 256>>>(gam, bet, B);
    dim3 gp((B + 2 * IT - 1) / (2 * IT), NJC);
    k_pair<<<gp, IT>>>(B);
    k_combine<<<(B + 255) / 256, 256>>>(B);
    k_final<<<(B + 255) / 256, 256>>>(out, B);
}

// round 7
// speedup vs baseline: 1.3701x; 1.0051x over previous
#include <cuda_runtime.h>
#include <math.h>

#define BMAX 8192
#define NJC 32
#define IT 128

// ---------------- scratch (device globals: no allocation allowed) ----------------
__device__ float  g_feat[BMAX * 784];
__device__ __align__(16) float g_proj_raw[BMAX * 4];
__device__ __align__(16) float g_proj[BMAX * 4];
__device__ __align__(16) float g_pn[BMAX * 4];
__device__ float  g_stats[8];
__device__ __align__(16) float g_wp[NJC * BMAX * 4];
__device__ float  g_srow[BMAX];
__device__ float  g_S;

// ================= K1: conv1+relu+pool + conv2+relu+pool (one image / block) =========
// R1 thread shape (grid-stride, 4 accumulators) — the only shape that schedules well.
// Change vs R1: row loads via float2 (8B-aligned since x0 and smem strides are even),
// halving LDS instruction count. FMA order IDENTICAL to R1 -> bit-exact proj chain.
__global__ __launch_bounds__(128) void k_conv(
    const float* __restrict__ x, const float* __restrict__ w1, const float* __restrict__ b1,
    const float* __restrict__ w2, const float* __restrict__ b2)
{
    __shared__ __align__(16) float xp[30 * 30];   // padded input 28x28 -> 30x30
    __shared__ __align__(16) float h1[8 * 16 * 16];
    __shared__ __align__(16) float sw1[72];
    __shared__ __align__(16) float sw2[1152];
    __shared__ float sb1[8], sb2[16];

    const int img = blockIdx.x;
    const int tid = threadIdx.x;

    for (int i = tid; i < 900; i += 128) xp[i] = 0.f;
    for (int i = tid; i < 2048; i += 128) h1[i] = 0.f;
    if (tid < 72) sw1[tid] = w1[tid];
    if (tid < 8)  sb1[tid] = b1[tid];
    for (int i = tid; i < 1152; i += 128) sw2[i] = w2[i];
    if (tid < 16) sb2[tid] = b2[tid];
    __syncthreads();

    const float* xi = x + (size_t)img * 784;
    for (int i = tid; i < 784; i += 128) {
        int y = i / 28, xx = i % 28;
        xp[(y + 1) * 30 + (xx + 1)] = xi[i];
    }
    __syncthreads();

    // conv1 (SAME, 3x3) + relu + 2x2 maxpool -> h1[c][1+py][1+px]
    for (int idx = tid; idx < 8 * 196; idx += 128) {
        int c = idx / 196, p = idx % 196;
        int py = p / 14, px = p % 14;
        int y0 = 2 * py, x0 = 2 * px;
        float v[4][4];
        #pragma unroll
        for (int dy = 0; dy < 4; dy++) {
            // offset (y0+dy)*30 + x0 is even -> 8B-aligned float2 loads
            const float2* rp = (const float2*)(xp + (y0 + dy) * 30 + x0);
            float2 a = rp[0], b = rp[1];
            v[dy][0] = a.x; v[dy][1] = a.y; v[dy][2] = b.x; v[dy][3] = b.y;
        }
        const float* w = sw1 + c * 9;
        float s00 = 0.f, s01 = 0.f, s10 = 0.f, s11 = 0.f;
        #pragma unroll
        for (int dy = 0; dy < 3; dy++)
            #pragma unroll
            for (int dx = 0; dx < 3; dx++) {
                float ww = w[dy * 3 + dx];
                s00 += ww * v[dy][dx];
                s01 += ww * v[dy][dx + 1];
                s10 += ww * v[dy + 1][dx];
                s11 += ww * v[dy + 1][dx + 1];
            }
        float m = fmaxf(fmaxf(s00, s01), fmaxf(s10, s11)) + sb1[c];
        h1[c * 256 + (py + 1) * 16 + (px + 1)] = fmaxf(m, 0.f);
    }
    __syncthreads();

    // conv2 (8->16, SAME, 3x3) + relu + 2x2 maxpool -> g_feat (flattened NCHW)
    float* fo = g_feat + (size_t)img * 784;
    for (int idx = tid; idx < 16 * 49; idx += 128) {
        int co = idx / 49, p = idx % 49;
        int py = p / 7, px = p % 7;
        int y0 = 2 * py, x0 = 2 * px;
        float s00 = 0.f, s01 = 0.f, s10 = 0.f, s11 = 0.f;
        #pragma unroll
        for (int ci = 0; ci < 8; ci++) {
            const float* w = sw2 + (co * 8 + ci) * 9;
            const float* hb = h1 + ci * 256;
            float v[4][4];
            #pragma unroll
            for (int dy = 0; dy < 4; dy++) {
                // offset (y0+dy)*16 + x0 is even -> 8B-aligned float2 loads
                const float2* rp = (const float2*)(hb + (y0 + dy) * 16 + x0);
                float2 a = rp[0], b = rp[1];
                v[dy][0] = a.x; v[dy][1] = a.y; v[dy][2] = b.x; v[dy][3] = b.y;
            }
            #pragma unroll
            for (int dy = 0; dy < 3; dy++)
                #pragma unroll
                for (int dx = 0; dx < 3; dx++) {
                    float ww = w[dy * 3 + dx];
                    s00 += ww * v[dy][dx];
                    s01 += ww * v[dy][dx + 1];
                    s10 += ww * v[dy + 1][dx];
                    s11 += ww * v[dy + 1][dx + 1];
                }
        }
        float m = fmaxf(fmaxf(s00, s01), fmaxf(s10, s11)) + sb2[co];
        fo[co * 49 + py * 7 + px] = fmaxf(m, 0.f);
    }
}

// ================= K2: fc1 (784->64, relu) + fc2 (64->4), 64 images / block ==========
#define KT 56
__global__ __launch_bounds__(256) void k_fc(
    const float* __restrict__ w1, const float* __restrict__ b1,
    const float* __restrict__ w2, const float* __restrict__ b2, int B)
{
    __shared__ float As[64][KT + 1];
    __shared__ float Ws[64][KT + 1];
    __shared__ float Hs[64][65];

    const int i0 = blockIdx.x * 64;
    const int tid = threadIdx.x;
    const int tx = tid & 15, ty = tid >> 4;

    float acc[4][4] = {};

    for (int k0 = 0; k0 < 784; k0 += KT) {
        for (int e = tid; e < 64 * KT; e += 256) {
            int r = e / KT, kk = e - r * KT;
            int row = i0 + r;
            As[r][kk] = (row < B) ? g_feat[(size_t)row * 784 + k0 + kk] : 0.f;
            Ws[r][kk] = w1[r * 784 + k0 + kk];
        }
        __syncthreads();
        #pragma unroll 4
        for (int kk = 0; kk < KT; kk++) {
            float a[4], b[4];
            #pragma unroll
            for (int r = 0; r < 4; r++) a[r] = As[ty * 4 + r][kk];
            #pragma unroll
            for (int c = 0; c < 4; c++) b[c] = Ws[tx * 4 + c][kk];
            #pragma unroll
            for (int r = 0; r < 4; r++)
                #pragma unroll
                for (int c = 0; c < 4; c++)
                    acc[r][c] += a[r] * b[c];
        }
        __syncthreads();
    }

    #pragma unroll
    for (int r = 0; r < 4; r++)
        #pragma unroll
        for (int c = 0; c < 4; c++) {
            int o = tx * 4 + c;
            Hs[ty * 4 + r][o] = fmaxf(acc[r][c] + b1[o], 0.f);
        }
    __syncthreads();

    int m = tid >> 2, c4 = tid & 3;
    if (i0 + m < B) {
        float s = b2[c4];
        #pragma unroll
        for (int o = 0; o < 64; o++) s += w2[c4 * 64 + o] * Hs[m][o];
        g_proj_raw[(size_t)(i0 + m) * 4 + c4] = s;
    }
}

// ================= K3: batchnorm stats (single block) =================
__global__ __launch_bounds__(1024) void k_bnstats(int B)
{
    __shared__ float red[32][8];
    const int tid = threadIdx.x;
    float s0 = 0, s1 = 0, s2 = 0, s3 = 0, q0 = 0, q1 = 0, q2 = 0, q3 = 0;
    const float4* pr = (const float4*)g_proj_raw;
    for (int i = tid; i < B; i += 1024) {
        float4 v = pr[i];
        s0 += v.x; s1 += v.y; s2 += v.z; s3 += v.w;
        q0 += v.x * v.x; q1 += v.y * v.y; q2 += v.z * v.z; q3 += v.w * v.w;
    }
    #pragma unroll
    for (int o = 16; o > 0; o >>= 1) {
        s0 += __shfl_down_sync(0xffffffffu, s0, o);
        s1 += __shfl_down_sync(0xffffffffu, s1, o);
        s2 += __shfl_down_sync(0xffffffffu, s2, o);
        s3 += __shfl_down_sync(0xffffffffu, s3, o);
        q0 += __shfl_down_sync(0xffffffffu, q0, o);
        q1 += __shfl_down_sync(0xffffffffu, q1, o);
        q2 += __shfl_down_sync(0xffffffffu, q2, o);
        q3 += __shfl_down_sync(0xffffffffu, q3, o);
    }
    int warp = tid >> 5, lane = tid & 31;
    if (lane == 0) {
        red[warp][0] = s0; red[warp][1] = s1; red[warp][2] = s2; red[warp][3] = s3;
        red[warp][4] = q0; red[warp][5] = q1; red[warp][6] = q2; red[warp][7] = q3;
    }
    __syncthreads();
    if (tid < 8) {
        float a = 0.f;
        for (int w = 0; w < 32; w++) a += red[w][tid];
        red[0][tid] = a;
    }
    __syncthreads();
    if (tid < 4) {
        float invB = 1.f / (float)B;
        float mean = red[0][tid] * invB;
        float var  = red[0][4 + tid] * invB - mean * mean;
        g_stats[tid] = mean;
        g_stats[4 + tid] = rsqrtf(var + 1e-5f);
    }
    if (tid == 0) g_S = 0.f;
}

// ================= K4: apply BN + row-normalize =================
__global__ __launch_bounds__(256) void k_bnapply(
    const float* __restrict__ gamma, const float* __restrict__ beta, int B)
{
    int i = blockIdx.x * 256 + threadIdx.x;
    if (i >= B) return;
    float4 v = ((const float4*)g_proj_raw)[i];
    float p0 = (v.x - g_stats[0]) * g_stats[4] * gamma[0] + beta[0];
    float p1 = (v.y - g_stats[1]) * g_stats[5] * gamma[1] + beta[1];
    float p2 = (v.z - g_stats[2]) * g_stats[6] * gamma[2] + beta[2];
    float p3 = (v.w - g_stats[3]) * g_stats[7] * gamma[3] + beta[3];
    float inv = 1.f / (sqrtf(p0 * p0 + p1 * p1 + p2 * p2 + p3 * p3) + 1e-12f);
    ((float4*)g_proj)[i] = make_float4(p0, p1, p2, p3);
    ((float4*)g_pn)[i]   = make_float4(p0 * inv, p1 * inv, p2 * inv, p3 * inv);
}

// ================= K5: pairwise adjacency-weighted sum =================
// 4 i-rows / thread; each shared-tile element load serves 4 pairs.
// Self-pair included (subtracted exactly in k_combine). Per-i j-order unchanged.
#define TJ 256
__global__ __launch_bounds__(IT) void k_pair(int B)
{
    __shared__ float4 pns[TJ];
    __shared__ float4 prs[TJ];
    const int tid = threadIdx.x;
    const int ib  = blockIdx.x * (4 * IT);
    const int jc  = blockIdx.y;
    const int chunk = (B + NJC - 1) / NJC;
    const int jbeg = jc * chunk;
    const int jend = min(jbeg + chunk, B);

    const float4* pn   = (const float4*)g_pn;
    const float4* proj = (const float4*)g_proj;

    float4 v[4];
    int    idx[4];
    #pragma unroll
    for (int r = 0; r < 4; r++) {
        idx[r] = ib + r * IT + tid;
        v[r] = (idx[r] < B) ? pn[idx[r]] : make_float4(0.f, 0.f, 0.f, 0.f);
    }
    float w0[4] = {}, w1[4] = {}, w2[4] = {}, w3[4] = {};

    for (int jb = jbeg; jb < jend; jb += TJ) {
        int n = jend - jb;
        for (int t = tid; t < TJ; t += IT) {
            if (t < n) { pns[t] = pn[jb + t]; prs[t] = proj[jb + t]; }
            else       { pns[t] = make_float4(0.f, 0.f, 0.f, 0.f);
                         prs[t] = make_float4(0.f, 0.f, 0.f, 0.f); }
        }
        __syncthreads();
        #pragma unroll 4
        for (int jj = 0; jj < TJ; jj++) {
            float4 q  = pns[jj];
            float4 pj = prs[jj];
            #pragma unroll
            for (int r = 0; r < 4; r++) {
                float d = v[r].x * q.x + v[r].y * q.y + v[r].z * q.z + v[r].w * q.w;
                float s = (d * d >= 0.9f) ? 1.f : 0.f;
                w0[r] = fmaf(s, pj.x, w0[r]); w1[r] = fmaf(s, pj.y, w1[r]);
                w2[r] = fmaf(s, pj.z, w2[r]); w3[r] = fmaf(s, pj.w, w3[r]);
            }
        }
        __syncthreads();
    }
    float4* wp = (float4*)g_wp;
    #pragma unroll
    for (int r = 0; r < 4; r++)
        if (idx[r] < B)
            wp[(size_t)jc * B + idx[r]] = make_float4(w0[r], w1[r], w2[r], w3[r]);
}

// ================= K6: combine partials (subtract self), row sums, diff^2 ==========
__global__ __launch_bounds__(256) void k_combine(int B)
{
    int i = blockIdx.x * 256 + threadIdx.x;
    float ds = 0.f;
    if (i < B) {
        const float4* wpp = (const float4*)g_wp;
        float4 w = wpp[i];
        #pragma unroll
        for (int jc = 1; jc < NJC; jc++) {
            float4 t = wpp[(size_t)jc * B + i];
            w.x += t.x; w.y += t.y; w.z += t.z; w.w += t.w;
        }
        float4 p = ((const float4*)g_proj)[i];
        // subtract self-pair contribution (off-diagonal mask in reference)
        w.x -= p.x; w.y -= p.y; w.z -= p.z; w.w -= p.w;
        g_srow[i] = p.x + p.y + p.z + p.w + w.x + w.y + w.z + w.w;
        float d0 = p.x - w.x, d1 = p.y - w.y, d2 = p.z - w.z, d3 = p.w - w.w;
        ds = d0 * d0 + d1 * d1 + d2 * d2 + d3 * d3;
    }
    #pragma unroll
    for (int o = 16; o > 0; o >>= 1) ds += __shfl_down_sync(0xffffffffu, ds, o);
    __shared__ float red[8];
    int warp = threadIdx.x >> 5, lane = threadIdx.x & 31;
    if (lane == 0) red[warp] = ds;
    __syncthreads();
    if (threadIdx.x == 0) {
        float t = 0.f;
        #pragma unroll
        for (int w = 0; w < 8; w++) t += red[w];
        atomicAdd(&g_S, t);
    }
}

// ================= K7: kernel value + sigmoid epilogue =================
__global__ __launch_bounds__(256) void k_final(float* __restrict__ out, int B)
{
    int i = blockIdx.x * 256 + threadIdx.x;
    if (i >= B) return;
    float kv = expf(-g_S);              // GAMMA = 1
    float logit = g_srow[i] + kv;       // SHIFT = 0
    float p = 1.f / (1.f + expf(-logit));
    out[2 * i]     = p;
    out[2 * i + 1] = 1.f - p;
}

// ================= launcher =================
extern "C" void kernel_launch(void* const* d_in, const int* in_sizes, int n_in,
                              void* d_out, int out_size)
{
    const float* x   = (const float*)d_in[0];
    const float* c1w = (const float*)d_in[1];
    const float* c1b = (const float*)d_in[2];
    const float* c2w = (const float*)d_in[3];
    const float* c2b = (const float*)d_in[4];
    const float* f1w = (const float*)d_in[5];
    const float* f1b = (const float*)d_in[6];
    const float* f2w = (const float*)d_in[7];
    const float* f2b = (const float*)d_in[8];
    const float* gam = (const float*)d_in[9];
    const float* bet = (const float*)d_in[10];
    float* out = (float*)d_out;

    const int B = in_sizes[0] / 784;

    k_conv<<<B, 128>>>(x, c1w, c1b, c2w, c2b);
    k_fc<<<(B + 63) / 64, 256>>>(f1w, f1b, f2w, f2b, B);
    k_bnstats<<<1, 1024>>>(B);
    k_bnapply<<<(B + 255) / 256, 256>>>(gam, bet, B);
    dim3 gp((B + 4 * IT - 1) / (4 * IT), NJC);
    k_pair<<<gp, IT>>>(B);
    k_combine<<<(B + 255) / 256, 256>>>(B);
    k_final<<<(B + 255) / 256, 256>>>(out, B);
}

// round 8
// speedup vs baseline: 1.6333x; 1.1921x over previous
#include <cuda_runtime.h>
#include <math.h>

#define BMAX 8192
#define NJC 32
#define IT 128

// h1 padded layout: row stride 22 floats (kills the stride-16 bank-conflict),
// 16 rows per channel -> channel stride 352.
#define H1S 22
#define H1C 352

// ---------------- scratch (device globals: no allocation allowed) ----------------
__device__ float  g_feat[BMAX * 784];
__device__ __align__(16) float g_proj_raw[BMAX * 4];
__device__ __align__(16) float g_proj[BMAX * 4];
__device__ __align__(16) float g_pn[BMAX * 4];
__device__ float  g_stats[8];
__device__ __align__(16) float g_wp[NJC * BMAX * 4];
__device__ float  g_srow[BMAX];
__device__ float  g_S;

// ================= K1: conv1+relu+pool + conv2+relu+pool (one image / block) =========
// R1 thread shape. Change vs R7: h1 row stride 16 -> 22 (bank-conflict padding).
// FMA order and all loaded values identical -> bit-exact proj chain.
__global__ __launch_bounds__(128) void k_conv(
    const float* __restrict__ x, const float* __restrict__ w1, const float* __restrict__ b1,
    const float* __restrict__ w2, const float* __restrict__ b2)
{
    __shared__ __align__(16) float xp[30 * 30];   // padded input 28x28 -> 30x30
    __shared__ __align__(16) float h1[8 * H1C];   // padded conv1 output, stride-22 rows
    __shared__ __align__(16) float sw1[72];
    __shared__ __align__(16) float sw2[1152];
    __shared__ float sb1[8], sb2[16];

    const int img = blockIdx.x;
    const int tid = threadIdx.x;

    for (int i = tid; i < 900; i += 128) xp[i] = 0.f;
    for (int i = tid; i < 8 * H1C; i += 128) h1[i] = 0.f;
    if (tid < 72) sw1[tid] = w1[tid];
    if (tid < 8)  sb1[tid] = b1[tid];
    for (int i = tid; i < 1152; i += 128) sw2[i] = w2[i];
    if (tid < 16) sb2[tid] = b2[tid];
    __syncthreads();

    const float* xi = x + (size_t)img * 784;
    for (int i = tid; i < 784; i += 128) {
        int y = i / 28, xx = i % 28;
        xp[(y + 1) * 30 + (xx + 1)] = xi[i];
    }
    __syncthreads();

    // conv1 (SAME, 3x3) + relu + 2x2 maxpool -> h1[c][1+py][1+px]
    for (int idx = tid; idx < 8 * 196; idx += 128) {
        int c = idx / 196, p = idx % 196;
        int py = p / 14, px = p % 14;
        int y0 = 2 * py, x0 = 2 * px;
        float v[4][4];
        #pragma unroll
        for (int dy = 0; dy < 4; dy++) {
            const float2* rp = (const float2*)(xp + (y0 + dy) * 30 + x0);
            float2 a = rp[0], b = rp[1];
            v[dy][0] = a.x; v[dy][1] = a.y; v[dy][2] = b.x; v[dy][3] = b.y;
        }
        const float* w = sw1 + c * 9;
        float s00 = 0.f, s01 = 0.f, s10 = 0.f, s11 = 0.f;
        #pragma unroll
        for (int dy = 0; dy < 3; dy++)
            #pragma unroll
            for (int dx = 0; dx < 3; dx++) {
                float ww = w[dy * 3 + dx];
                s00 += ww * v[dy][dx];
                s01 += ww * v[dy][dx + 1];
                s10 += ww * v[dy + 1][dx];
                s11 += ww * v[dy + 1][dx + 1];
            }
        float m = fmaxf(fmaxf(s00, s01), fmaxf(s10, s11)) + sb1[c];
        h1[c * H1C + (py + 1) * H1S + (px + 1)] = fmaxf(m, 0.f);
    }
    __syncthreads();

    // conv2 (8->16, SAME, 3x3) + relu + 2x2 maxpool -> g_feat (flattened NCHW)
    float* fo = g_feat + (size_t)img * 784;
    for (int idx = tid; idx < 16 * 49; idx += 128) {
        int co = idx / 49, p = idx % 49;
        int py = p / 7, px = p % 7;
        int y0 = 2 * py, x0 = 2 * px;
        float s00 = 0.f, s01 = 0.f, s10 = 0.f, s11 = 0.f;
        #pragma unroll
        for (int ci = 0; ci < 8; ci++) {
            const float* w = sw2 + (co * 8 + ci) * 9;
            const float* hb = h1 + ci * H1C;
            float v[4][4];
            #pragma unroll
            for (int dy = 0; dy < 4; dy++) {
                // (y0+dy)*22 + x0 is even -> aligned float2; bank = (12py+22dy+2px)%32,
                // py-dependent -> conflicts collapse from ~4.6-way to <=2-way.
                const float2* rp = (const float2*)(hb + (y0 + dy) * H1S + x0);
                float2 a = rp[0], b = rp[1];
                v[dy][0] = a.x; v[dy][1] = a.y; v[dy][2] = b.x; v[dy][3] = b.y;
            }
            #pragma unroll
            for (int dy = 0; dy < 3; dy++)
                #pragma unroll
                for (int dx = 0; dx < 3; dx++) {
                    float ww = w[dy * 3 + dx];
                    s00 += ww * v[dy][dx];
                    s01 += ww * v[dy][dx + 1];
                    s10 += ww * v[dy + 1][dx];
                    s11 += ww * v[dy + 1][dx + 1];
                }
        }
        float m = fmaxf(fmaxf(s00, s01), fmaxf(s10, s11)) + sb2[co];
        fo[co * 49 + py * 7 + px] = fmaxf(m, 0.f);
    }
}

// ================= K2: fc1 (784->64, relu) + fc2 (64->4), 64 images / block ==========
#define KT 56
__global__ __launch_bounds__(256) void k_fc(
    const float* __restrict__ w1, const float* __restrict__ b1,
    const float* __restrict__ w2, const float* __restrict__ b2, int B)
{
    __shared__ float As[64][KT + 1];
    __shared__ float Ws[64][KT + 1];
    __shared__ float Hs[64][65];

    const int i0 = blockIdx.x * 64;
    const int tid = threadIdx.x;
    const int tx = tid & 15, ty = tid >> 4;

    float acc[4][4] = {};

    for (int k0 = 0; k0 < 784; k0 += KT) {
        for (int e = tid; e < 64 * KT; e += 256) {
            int r = e / KT, kk = e - r * KT;
            int row = i0 + r;
            As[r][kk] = (row < B) ? g_feat[(size_t)row * 784 + k0 + kk] : 0.f;
            Ws[r][kk] = w1[r * 784 + k0 + kk];
        }
        __syncthreads();
        #pragma unroll 4
        for (int kk = 0; kk < KT; kk++) {
            float a[4], b[4];
            #pragma unroll
            for (int r = 0; r < 4; r++) a[r] = As[ty * 4 + r][kk];
            #pragma unroll
            for (int c = 0; c < 4; c++) b[c] = Ws[tx * 4 + c][kk];
            #pragma unroll
            for (int r = 0; r < 4; r++)
                #pragma unroll
                for (int c = 0; c < 4; c++)
                    acc[r][c] += a[r] * b[c];
        }
        __syncthreads();
    }

    #pragma unroll
    for (int r = 0; r < 4; r++)
        #pragma unroll
        for (int c = 0; c < 4; c++) {
            int o = tx * 4 + c;
            Hs[ty * 4 + r][o] = fmaxf(acc[r][c] + b1[o], 0.f);
        }
    __syncthreads();

    int m = tid >> 2, c4 = tid & 3;
    if (i0 + m < B) {
        float s = b2[c4];
        #pragma unroll
        for (int o = 0; o < 64; o++) s += w2[c4 * 64 + o] * Hs[m][o];
        g_proj_raw[(size_t)(i0 + m) * 4 + c4] = s;
    }
}

// ================= K3: batchnorm stats (single block) =================
__global__ __launch_bounds__(1024) void k_bnstats(int B)
{
    __shared__ float red[32][8];
    const int tid = threadIdx.x;
    float s0 = 0, s1 = 0, s2 = 0, s3 = 0, q0 = 0, q1 = 0, q2 = 0, q3 = 0;
    const float4* pr = (const float4*)g_proj_raw;
    for (int i = tid; i < B; i += 1024) {
        float4 v = pr[i];
        s0 += v.x; s1 += v.y; s2 += v.z; s3 += v.w;
        q0 += v.x * v.x; q1 += v.y * v.y; q2 += v.z * v.z; q3 += v.w * v.w;
    }
    #pragma unroll
    for (int o = 16; o > 0; o >>= 1) {
        s0 += __shfl_down_sync(0xffffffffu, s0, o);
        s1 += __shfl_down_sync(0xffffffffu, s1, o);
        s2 += __shfl_down_sync(0xffffffffu, s2, o);
        s3 += __shfl_down_sync(0xffffffffu, s3, o);
        q0 += __shfl_down_sync(0xffffffffu, q0, o);
        q1 += __shfl_down_sync(0xffffffffu, q1, o);
        q2 += __shfl_down_sync(0xffffffffu, q2, o);
        q3 += __shfl_down_sync(0xffffffffu, q3, o);
    }
    int warp = tid >> 5, lane = tid & 31;
    if (lane == 0) {
        red[warp][0] = s0; red[warp][1] = s1; red[warp][2] = s2; red[warp][3] = s3;
        red[warp][4] = q0; red[warp][5] = q1; red[warp][6] = q2; red[warp][7] = q3;
    }
    __syncthreads();
    if (tid < 8) {
        float a = 0.f;
        for (int w = 0; w < 32; w++) a += red[w][tid];
        red[0][tid] = a;
    }
    __syncthreads();
    if (tid < 4) {
        float invB = 1.f / (float)B;
        float mean = red[0][tid] * invB;
        float var  = red[0][4 + tid] * invB - mean * mean;
        g_stats[tid] = mean;
        g_stats[4 + tid] = rsqrtf(var + 1e-5f);
    }
    if (tid == 0) g_S = 0.f;
}

// ================= K4: apply BN + row-normalize =================
__global__ __launch_bounds__(256) void k_bnapply(
    const float* __restrict__ gamma, const float* __restrict__ beta, int B)
{
    int i = blockIdx.x * 256 + threadIdx.x;
    if (i >= B) return;
    float4 v = ((const float4*)g_proj_raw)[i];
    float p0 = (v.x - g_stats[0]) * g_stats[4] * gamma[0] + beta[0];
    float p1 = (v.y - g_stats[1]) * g_stats[5] * gamma[1] + beta[1];
    float p2 = (v.z - g_stats[2]) * g_stats[6] * gamma[2] + beta[2];
    float p3 = (v.w - g_stats[3]) * g_stats[7] * gamma[3] + beta[3];
    float inv = 1.f / (sqrtf(p0 * p0 + p1 * p1 + p2 * p2 + p3 * p3) + 1e-12f);
    ((float4*)g_proj)[i] = make_float4(p0, p1, p2, p3);
    ((float4*)g_pn)[i]   = make_float4(p0 * inv, p1 * inv, p2 * inv, p3 * inv);
}

// ================= K5: pairwise adjacency-weighted sum =================
// 4 i-rows / thread; self-pair included (subtracted exactly in k_combine).
#define TJ 256
__global__ __launch_bounds__(IT) void k_pair(int B)
{
    __shared__ float4 pns[TJ];
    __shared__ float4 prs[TJ];
    const int tid = threadIdx.x;
    const int ib  = blockIdx.x * (4 * IT);
    const int jc  = blockIdx.y;
    const int chunk = (B + NJC - 1) / NJC;
    const int jbeg = jc * chunk;
    const int jend = min(jbeg + chunk, B);

    const float4* pn   = (const float4*)g_pn;
    const float4* proj = (const float4*)g_proj;

    float4 v[4];
    int    idx[4];
    #pragma unroll
    for (int r = 0; r < 4; r++) {
        idx[r] = ib + r * IT + tid;
        v[r] = (idx[r] < B) ? pn[idx[r]] : make_float4(0.f, 0.f, 0.f, 0.f);
    }
    float w0[4] = {}, w1[4] = {}, w2[4] = {}, w3[4] = {};

    for (int jb = jbeg; jb < jend; jb += TJ) {
        int n = jend - jb;
        for (int t = tid; t < TJ; t += IT) {
            if (t < n) { pns[t] = pn[jb + t]; prs[t] = proj[jb + t]; }
            else       { pns[t] = make_float4(0.f, 0.f, 0.f, 0.f);
                         prs[t] = make_float4(0.f, 0.f, 0.f, 0.f); }
        }
        __syncthreads();
        #pragma unroll 4
        for (int jj = 0; jj < TJ; jj++) {
            float4 q  = pns[jj];
            float4 pj = prs[jj];
            #pragma unroll
            for (int r = 0; r < 4; r++) {
                float d = v[r].x * q.x + v[r].y * q.y + v[r].z * q.z + v[r].w * q.w;
                float s = (d * d >= 0.9f) ? 1.f : 0.f;
                w0[r] = fmaf(s, pj.x, w0[r]); w1[r] = fmaf(s, pj.y, w1[r]);
                w2[r] = fmaf(s, pj.z, w2[r]); w3[r] = fmaf(s, pj.w, w3[r]);
            }
        }
        __syncthreads();
    }
    float4* wp = (float4*)g_wp;
    #pragma unroll
    for (int r = 0; r < 4; r++)
        if (idx[r] < B)
            wp[(size_t)jc * B + idx[r]] = make_float4(w0[r], w1[r], w2[r], w3[r]);
}

// ================= K6: combine partials (subtract self), row sums, diff^2 ==========
__global__ __launch_bounds__(256) void k_combine(int B)
{
    int i = blockIdx.x * 256 + threadIdx.x;
    float ds = 0.f;
    if (i < B) {
        const float4* wpp = (const float4*)g_wp;
        float4 w = wpp[i];
        #pragma unroll
        for (int jc = 1; jc < NJC; jc++) {
            float4 t = wpp[(size_t)jc * B + i];
            w.x += t.x; w.y += t.y; w.z += t.z; w.w += t.w;
        }
        float4 p = ((const float4*)g_proj)[i];
        // subtract self-pair contribution (off-diagonal mask in reference)
        w.x -= p.x; w.y -= p.y; w.z -= p.z; w.w -= p.w;
        g_srow[i] = p.x + p.y + p.z + p.w + w.x + w.y + w.z + w.w;
        float d0 = p.x - w.x, d1 = p.y - w.y, d2 = p.z - w.z, d3 = p.w - w.w;
        ds = d0 * d0 + d1 * d1 + d2 * d2 + d3 * d3;
    }
    #pragma unroll
    for (int o = 16; o > 0; o >>= 1) ds += __shfl_down_sync(0xffffffffu, ds, o);
    __shared__ float red[8];
    int warp = threadIdx.x >> 5, lane = threadIdx.x & 31;
    if (lane == 0) red[warp] = ds;
    __syncthreads();
    if (threadIdx.x == 0) {
        float t = 0.f;
        #pragma unroll
        for (int w = 0; w < 8; w++) t += red[w];
        atomicAdd(&g_S, t);
    }
}

// ================= K7: kernel value + sigmoid epilogue =================
__global__ __launch_bounds__(256) void k_final(float* __restrict__ out, int B)
{
    int i = blockIdx.x * 256 + threadIdx.x;
    if (i >= B) return;
    float kv = expf(-g_S);              // GAMMA = 1
    float logit = g_srow[i] + kv;       // SHIFT = 0
    float p = 1.f / (1.f + expf(-logit));
    out[2 * i]     = p;
    out[2 * i + 1] = 1.f - p;
}

// ================= launcher =================
extern "C" void kernel_launch(void* const* d_in, const int* in_sizes, int n_in,
                              void* d_out, int out_size)
{
    const float* x   = (const float*)d_in[0];
    const float* c1w = (const float*)d_in[1];
    const float* c1b = (const float*)d_in[2];
    const float* c2w = (const float*)d_in[3];
    const float* c2b = (const float*)d_in[4];
    const float* f1w = (const float*)d_in[5];
    const float* f1b = (const float*)d_in[6];
    const float* f2w = (const float*)d_in[7];
    const float* f2b = (const float*)d_in[8];
    const float* gam = (const float*)d_in[9];
    const float* bet = (const float*)d_in[10];
    float* out = (float*)d_out;

    const int B = in_sizes[0] / 784;

    k_conv<<<B, 128>>>(x, c1w, c1b, c2w, c2b);
    k_fc<<<(B + 63) / 64, 256>>>(f1w, f1b, f2w, f2b, B);
    k_bnstats<<<1, 1024>>>(B);
    k_bnapply<<<(B + 255) / 256, 256>>>(gam, bet, B);
    dim3 gp((B + 4 * IT - 1) / (4 * IT), NJC);
    k_pair<<<gp, IT>>>(B);
    k_combine<<<(B + 255) / 256, 256>>>(B);
    k_final<<<(B + 255) / 256, 256>>>(out, B);
}